// round 1
// baseline (speedup 1.0000x reference)
#include <cuda_runtime.h>

#define B_   16
#define N_   128
#define M_   1024
#define DN_  512
#define DE_  256
#define WN_  128
#define WE_  128
#define P_   512
#define HID_ 256

// ------------------------- scratch (device globals) -------------------------
__device__ float d_XW  [B_*N_*WN_];     // X@Wn  (row-masked)
__device__ float d_XW2 [B_*N_*WN_];     // X@Wn2 (row-masked)
__device__ float d_h   [B_*N_*WN_];     // relu(A@XW)*mask
__device__ float d_agg [B_*N_*WE_];     // scatter(g, src)*mask
__device__ float d_Eg  [B_*M_*DE_];     // gathered edge feats * emask
__device__ float d_EgWe[B_*M_*WE_];     // Eg@We
__device__ float d_g   [B_*M_*WE_];     // relu(L@EgWe)*emask
__device__ float d_EFp [B_*P_*DE_];     // edge_features at pairs
__device__ float d_ci  [B_*P_*512];     // classifier input (Q GEMM writes cols 384..511)
__device__ float d_hid [B_*P_*768];     // fused layer-1 hidden (lr|cr|mr)
__device__ float d_W1c [512*768];       // concat(lr_W1, scr_W1, mr_W1)
__device__ float d_b1c [768];

// ------------------------- generic tiled fp32 GEMM --------------------------
// C[M,N] = A[M,K] @ B[K,N] ; optional bias (per col), relu, and row-mask
// (row r is zeroed when (r % rpb) >= rowcnt[r / rpb]).
// Requires M%64==0, N%64==0, K%16==0. C has leading dim ldc.
__global__ void sgemm64(const float* __restrict__ A, const float* __restrict__ Bw,
                        float* __restrict__ C, int M, int N, int K, int ldc,
                        const float* __restrict__ bias, int relu,
                        const int* __restrict__ rowcnt, int rpb)
{
    __shared__ float As[16][64];
    __shared__ float Bs[16][64];
    const int tid = threadIdx.x;             // 256 threads
    const int bx = blockIdx.x, by = blockIdx.y;
    const int tx = tid & 15, ty = tid >> 4;
    const int a_row = tid >> 2, a_col = (tid & 3) << 2;
    const int b_row = tid >> 4, b_col = (tid & 15) << 2;

    const float* Ab = A + (size_t)(by * 64) * K;
    const float* Bb = Bw + (size_t)(bx * 64);

    float acc[4][4] = {};
    for (int k0 = 0; k0 < K; k0 += 16) {
        float4 av = *(const float4*)(Ab + (size_t)a_row * K + k0 + a_col);
        As[a_col + 0][a_row] = av.x;
        As[a_col + 1][a_row] = av.y;
        As[a_col + 2][a_row] = av.z;
        As[a_col + 3][a_row] = av.w;
        *(float4*)&Bs[b_row][b_col] =
            *(const float4*)(Bb + (size_t)(k0 + b_row) * N + b_col);
        __syncthreads();
#pragma unroll
        for (int k = 0; k < 16; k++) {
            float a0 = As[k][ty * 4 + 0], a1 = As[k][ty * 4 + 1];
            float a2 = As[k][ty * 4 + 2], a3 = As[k][ty * 4 + 3];
            float b0 = Bs[k][tx * 4 + 0], b1 = Bs[k][tx * 4 + 1];
            float b2 = Bs[k][tx * 4 + 2], b3 = Bs[k][tx * 4 + 3];
            acc[0][0] += a0 * b0; acc[0][1] += a0 * b1; acc[0][2] += a0 * b2; acc[0][3] += a0 * b3;
            acc[1][0] += a1 * b0; acc[1][1] += a1 * b1; acc[1][2] += a1 * b2; acc[1][3] += a1 * b3;
            acc[2][0] += a2 * b0; acc[2][1] += a2 * b1; acc[2][2] += a2 * b2; acc[2][3] += a2 * b3;
            acc[3][0] += a3 * b0; acc[3][1] += a3 * b1; acc[3][2] += a3 * b2; acc[3][3] += a3 * b3;
        }
        __syncthreads();
    }
#pragma unroll
    for (int i = 0; i < 4; i++) {
        int row = by * 64 + ty * 4 + i;
        float mask = 1.0f;
        if (rowcnt) {
            int bb = row / rpb, nn = row % rpb;
            if (nn >= rowcnt[bb]) mask = 0.0f;
        }
#pragma unroll
        for (int j = 0; j < 4; j++) {
            int col = bx * 64 + tx * 4 + j;
            float v = acc[i][j];
            if (bias) v += bias[col];
            if (relu) v = fmaxf(v, 0.0f);
            C[(size_t)row * ldc + col] = v * mask;
        }
    }
}

// ------------------------- Eg gather: Eg[b,m] = EF[b,src,dst]*emask ---------
__global__ void eg_gather(const float* __restrict__ EF, const int* __restrict__ eidx,
                          const int* __restrict__ nedg, float* __restrict__ Eg)
{
    int b = blockIdx.x / M_, m = blockIdx.x % M_;
    int s = eidx[(b * 2 + 0) * M_ + m];
    int d = eidx[(b * 2 + 1) * M_ + m];
    bool on = m < nedg[b];
    const float4* src = (const float4*)(EF + (((size_t)b * N_ + s) * N_ + d) * DE_);
    float4* dst = (float4*)(Eg + ((size_t)b * M_ + m) * DE_);
    float4 z = make_float4(0.f, 0.f, 0.f, 0.f);
    for (int t = threadIdx.x; t < DE_ / 4; t += blockDim.x)
        dst[t] = on ? src[t] : z;
}

// ------------------------- h = relu(XW_i + sum_j adj_ij * XW_j) * mask ------
__global__ void h_kernel(const float* __restrict__ XW, const float* __restrict__ adj,
                         const int* __restrict__ nobj, float* __restrict__ h)
{
    int b = blockIdx.x / N_, i = blockIdx.x % N_;
    int w = threadIdx.x;                    // 128
    __shared__ float arow[N_];
    arow[w] = adj[((size_t)b * N_ + i) * N_ + w];
    __syncthreads();
    const float* XWb = XW + (size_t)b * N_ * WN_;
    float acc = XWb[i * WN_ + w];           // identity term (XW already row-masked)
    for (int j = 0; j < N_; j++) {
        float a = arow[j];
        if (a != 0.0f) acc += a * XWb[j * WN_ + w];
    }
    h[((size_t)b * N_ + i) * WN_ + w] = (i < nobj[b]) ? fmaxf(acc, 0.0f) : 0.0f;
}

// ----------- g = relu(EgWe_m + sum_k L_mk * EgWe_k) * emask (sparse L) ------
__global__ void g_kernel(const float* __restrict__ EgWe, const float* __restrict__ ladj,
                         const int* __restrict__ nedg, float* __restrict__ g)
{
    int b = blockIdx.x / M_, m = blockIdx.x % M_;
    int w = threadIdx.x;                    // 128
    __shared__ int   s_idx[M_];
    __shared__ float s_val[M_];
    __shared__ int   s_cnt[129];

    const float* Lrow = ladj + ((size_t)b * M_ + m) * M_;
    float v[8];
    int cnt = 0;
    int base = w * 8;
#pragma unroll
    for (int t = 0; t < 8; t++) {
        v[t] = Lrow[base + t];
        if (v[t] != 0.0f) cnt++;
    }
    s_cnt[w + 1] = cnt;
    if (w == 0) s_cnt[0] = 0;
    __syncthreads();
    if (w == 0)
        for (int t = 1; t <= 128; t++) s_cnt[t] += s_cnt[t - 1];
    __syncthreads();
    int pos = s_cnt[w];
#pragma unroll
    for (int t = 0; t < 8; t++)
        if (v[t] != 0.0f) { s_idx[pos] = base + t; s_val[pos] = v[t]; pos++; }
    __syncthreads();
    int total = s_cnt[128];
    const float* Eb = EgWe + (size_t)b * M_ * WE_;
    float acc = Eb[m * WE_ + w];            // identity term (EgWe row-masked via Eg)
    for (int p = 0; p < total; p++)
        acc += s_val[p] * Eb[s_idx[p] * WE_ + w];
    g[((size_t)b * M_ + m) * WE_ + w] = (m < nedg[b]) ? fmaxf(acc, 0.0f) : 0.0f;
}

// ----------- agg[b,n] = sum_{m: src==n} g[b,m] ; * nmask (deterministic) ----
__global__ void agg_kernel(const float* __restrict__ g, const int* __restrict__ eidx,
                           const int* __restrict__ nobj, float* __restrict__ agg)
{
    int b = blockIdx.x / N_, n = blockIdx.x % N_;
    int w = threadIdx.x;                    // 128
    __shared__ int ssrc[M_];
    for (int t = w; t < M_; t += 128) ssrc[t] = eidx[(b * 2 + 0) * M_ + t];
    __syncthreads();
    float acc = 0.0f;
    const float* gb = g + (size_t)b * M_ * WE_;
    for (int m = 0; m < M_; m++)
        if (ssrc[m] == n) acc += gb[m * WE_ + w];
    agg[((size_t)b * N_ + n) * WE_ + w] = (n < nobj[b]) ? acc : 0.0f;
}

// ------------------------- edge feats gathered at pairs ---------------------
__global__ void efp_gather(const float* __restrict__ EF, const int* __restrict__ pairs,
                           float* __restrict__ EFp)
{
    int b = blockIdx.x / P_, p = blockIdx.x % P_;
    int p0 = pairs[((size_t)b * P_ + p) * 2 + 0];
    int p1 = pairs[((size_t)b * P_ + p) * 2 + 1];
    const float4* src = (const float4*)(EF + (((size_t)b * N_ + p0) * N_ + p1) * DE_);
    float4* dst = (float4*)(EFp + ((size_t)b * P_ + p) * DE_);
    for (int t = threadIdx.x; t < DE_ / 4; t += blockDim.x)
        dst[t] = src[t];
}

// ------------------------- ci assembly (cols 0..383) ------------------------
__global__ void ci_kernel(const float* __restrict__ h, const float* __restrict__ agg,
                          const float* __restrict__ XW2, const int* __restrict__ pairs,
                          float* __restrict__ ci)
{
    int b = blockIdx.x / P_, p = blockIdx.x % P_;
    int w = threadIdx.x;                    // 128
    int p0 = pairs[((size_t)b * P_ + p) * 2 + 0];
    int p1 = pairs[((size_t)b * P_ + p) * 2 + 1];
    const float* hb = h   + (size_t)b * N_ * WN_;
    const float* ab = agg + (size_t)b * N_ * WE_;
    const float* xb = XW2 + (size_t)b * N_ * WN_;
    float* crow = ci + ((size_t)b * P_ + p) * 512;
    crow[w]        = hb[p0 * WN_ + w] + hb[p1 * WN_ + w];
    crow[128 + w]  = ab[p0 * WE_ + w] + ab[p1 * WE_ + w];
    crow[256 + w]  = fmaxf(xb[p0 * WN_ + w] + xb[p1 * WN_ + w], 0.0f);  // Pm
    // crow[384..511] = Q, written by the pair-Q GEMM
}

// ------------------------- concat W1 / b1 (lr | scr | mr) -------------------
__global__ void catw1(const float* __restrict__ lrW1, const float* __restrict__ scrW1,
                      const float* __restrict__ mrW1, const float* __restrict__ lrb1,
                      const float* __restrict__ scrb1, const float* __restrict__ mrb1,
                      float* __restrict__ W1c, float* __restrict__ b1c)
{
    int k = blockIdx.x, c = threadIdx.x;    // 512 blocks, 256 threads
    W1c[k * 768 + c]       = lrW1 [k * 256 + c];
    W1c[k * 768 + 256 + c] = scrW1[k * 256 + c];
    W1c[k * 768 + 512 + c] = mrW1 [k * 256 + c];
    if (k == 0) {
        b1c[c]       = lrb1[c];
        b1c[256 + c] = scrb1[c];
        b1c[512 + c] = mrb1[c];
    }
}

// ------------------------- second layer: 3 heads, 32 outputs/pair -----------
__global__ void head2_kernel(const float* __restrict__ hid,
                             const float* __restrict__ lrW2, const float* __restrict__ lrb2,
                             const float* __restrict__ crW2, const float* __restrict__ crb2,
                             const float* __restrict__ mrW2, const float* __restrict__ mrb2,
                             float* __restrict__ out)
{
    __shared__ float sh[8 * 768];
    int tid = threadIdx.x;                  // 256
    const float* src = hid + (size_t)blockIdx.x * 8 * 768;
    for (int i = tid; i < 8 * 768 / 4; i += 256)
        ((float4*)sh)[i] = ((const float4*)src)[i];
    __syncthreads();
    int lp = tid / 32, j = tid % 32;
    int pr = blockIdx.x * 8 + lp;
    const float* W2; float bias; int nout, oj; const float* hr; size_t obase;
    if (j < 9)       { W2 = lrW2; oj = j;      bias = lrb2[oj]; nout = 9;  hr = sh + lp * 768;       obase = 0; }
    else if (j < 15) { W2 = crW2; oj = j - 9;  bias = crb2[oj]; nout = 6;  hr = sh + lp * 768 + 256; obase = (size_t)B_ * P_ * 9; }
    else             { W2 = mrW2; oj = j - 15; bias = mrb2[oj]; nout = 17; hr = sh + lp * 768 + 512; obase = (size_t)B_ * P_ * 15; }
    float acc = bias;
#pragma unroll 8
    for (int k = 0; k < 256; k++)
        acc += hr[k] * W2[k * nout + oj];
    out[obase + (size_t)pr * nout + oj] = acc;
}

// ============================================================================
extern "C" void kernel_launch(void* const* d_in, const int* in_sizes, int n_in,
                              void* d_out, int out_size)
{
    const float* NF    = (const float*)d_in[0];
    const float* EF    = (const float*)d_in[1];
    const float* ADJ   = (const float*)d_in[2];
    const float* LADJ  = (const float*)d_in[3];
    const int*   EIDX  = (const int*)  d_in[4];
    const int*   PAIRS = (const int*)  d_in[5];
    const int*   NOBJ  = (const int*)  d_in[6];
    const int*   NEDG  = (const int*)  d_in[7];
    const float* Wn    = (const float*)d_in[8];
    const float* We    = (const float*)d_in[9];
    const float* Wn2   = (const float*)d_in[10];
    const float* We2   = (const float*)d_in[11];
    const float* scrW1 = (const float*)d_in[12];
    const float* scrb1 = (const float*)d_in[13];
    const float* scrW2 = (const float*)d_in[14];
    const float* scrb2 = (const float*)d_in[15];
    const float* lrW1  = (const float*)d_in[16];
    const float* lrb1  = (const float*)d_in[17];
    const float* lrW2  = (const float*)d_in[18];
    const float* lrb2  = (const float*)d_in[19];
    const float* mrW1  = (const float*)d_in[20];
    const float* mrb1  = (const float*)d_in[21];
    const float* mrW2  = (const float*)d_in[22];
    const float* mrb2  = (const float*)d_in[23];
    float* out = (float*)d_out;

    float *XW, *XW2, *h, *agg, *Eg, *EgWe, *g, *EFp, *ci, *hid, *W1c, *b1c;
    cudaGetSymbolAddress((void**)&XW,   d_XW);
    cudaGetSymbolAddress((void**)&XW2,  d_XW2);
    cudaGetSymbolAddress((void**)&h,    d_h);
    cudaGetSymbolAddress((void**)&agg,  d_agg);
    cudaGetSymbolAddress((void**)&Eg,   d_Eg);
    cudaGetSymbolAddress((void**)&EgWe, d_EgWe);
    cudaGetSymbolAddress((void**)&g,    d_g);
    cudaGetSymbolAddress((void**)&EFp,  d_EFp);
    cudaGetSymbolAddress((void**)&ci,   d_ci);
    cudaGetSymbolAddress((void**)&hid,  d_hid);
    cudaGetSymbolAddress((void**)&W1c,  d_W1c);
    cudaGetSymbolAddress((void**)&b1c,  d_b1c);

    // weight concat (independent of data path)
    catw1<<<512, 256>>>(lrW1, scrW1, mrW1, lrb1, scrb1, mrb1, W1c, b1c);

    // XW = mask(NF @ Wn), XW2 = mask(NF @ Wn2)   [M=2048, K=512, N=128]
    sgemm64<<<dim3(2, 32), 256>>>(NF, Wn,  XW,  B_ * N_, WN_, DN_, WN_, nullptr, 0, NOBJ, N_);
    sgemm64<<<dim3(2, 32), 256>>>(NF, Wn2, XW2, B_ * N_, WN_, DN_, WN_, nullptr, 0, NOBJ, N_);

    // Eg gather + EgWe = Eg @ We                  [M=16384, K=256, N=128]
    eg_gather<<<B_ * M_, 64>>>(EF, EIDX, NEDG, Eg);
    sgemm64<<<dim3(2, 256), 256>>>(Eg, We, EgWe, B_ * M_, WE_, DE_, WE_, nullptr, 0, nullptr, 0);

    // graph convs (sparse propagate)
    h_kernel<<<B_ * N_, 128>>>(XW, ADJ, NOBJ, h);
    g_kernel<<<B_ * M_, 128>>>(EgWe, LADJ, NEDG, g);

    // scatter-add g by src (deterministic)
    agg_kernel<<<B_ * N_, 128>>>(g, EIDX, NOBJ, agg);

    // pair-wise features
    efp_gather<<<B_ * P_, 64>>>(EF, PAIRS, EFp);
    ci_kernel<<<B_ * P_, 128>>>(h, agg, XW2, PAIRS, ci);
    // Q = relu(EFp @ We2) directly into ci cols [384:512)   [M=8192, K=256, N=128]
    sgemm64<<<dim3(2, 128), 256>>>(EFp, We2, ci + 384, B_ * P_, WE_, DE_, 512, nullptr, 1, nullptr, 0);

    // fused layer-1: hid = relu(ci @ W1c + b1c)  [M=8192, K=512, N=768]
    sgemm64<<<dim3(12, 128), 256>>>(ci, W1c, hid, B_ * P_, 768, 512, 768, b1c, 1, nullptr, 0);

    // layer-2 heads -> out (lr | cr | mr, flattened in order)
    head2_kernel<<<B_ * P_ / 8, 256>>>(hid, lrW2, lrb2, scrW2, scrb2, mrW2, mrb2, out);
}

// round 2
// speedup vs baseline: 1.2641x; 1.2641x over previous
#include <cuda_runtime.h>

#define B_   16
#define N_   128
#define M_   1024
#define DN_  512
#define DE_  256
#define WN_  128
#define WE_  128
#define P_   512

// ------------------------- scratch (device globals) -------------------------
__device__ float d_XW   [B_*N_*WN_];     // X@Wn  (row-masked)
__device__ float d_XW2  [B_*N_*WN_];     // X@Wn2 (row-masked)
__device__ float d_nemb [B_*N_*256];     // [h | agg] per node
__device__ float d_nodeY[B_*N_*768];     // nemb @ W1c[0:256]
__device__ float d_Eg   [B_*M_*DE_];     // gathered edge feats * emask
__device__ float d_EgWe [B_*M_*WE_];     // Eg@We
__device__ float d_g    [B_*M_*WE_];     // relu(L@EgWe)*emask
__device__ float d_EFp  [B_*P_*DE_];     // edge_features at pairs
__device__ float d_pf   [B_*P_*256];     // [Pm | Q] per pair
__device__ float d_hidB [B_*P_*768];     // pf @ W1c[256:512] + b1c (no relu)
__device__ float d_W1c  [512*768];       // concat(lr_W1, scr_W1, mr_W1) along cols
__device__ float d_b1c  [768];

// ===================== 128x128 tiled fp32 GEMM, 8x8/thread ==================
// C[M,N] = A[M,K] @ B[K,N] (+bias, relu, row-mask). M%128==0, N%128==0, K%8==0.
__global__ __launch_bounds__(256)
void sgemm128(const float* __restrict__ A, const float* __restrict__ Bw,
              float* __restrict__ C, int M, int N, int K, int ldc,
              const float* __restrict__ bias, int relu,
              const int* __restrict__ rowcnt, int rpb)
{
    __shared__ float As[8][128];
    __shared__ float Bs[8][128];
    const int tid = threadIdx.x;
    const int m0 = blockIdx.y * 128, n0 = blockIdx.x * 128;
    const int ar = tid >> 1, ak = (tid & 1) * 4;   // A-load: row in tile, k-quad
    const int br = tid >> 5, bc = (tid & 31) * 4;  // B-load: k-row, col-quad
    const int tr = tid >> 4, tc = tid & 15;        // compute thread grid 16x16

    const float* Aptr = A + (size_t)(m0 + ar) * K + ak;
    const float* Bptr = Bw + (size_t)br * N + n0 + bc;

    float4 a_pref = *(const float4*)Aptr;
    float4 b_pref = *(const float4*)Bptr;

    float acc[8][8] = {};
    float a_frag[8], b_frag[8];

    for (int k0 = 0; k0 < K; k0 += 8) {
        As[ak + 0][ar] = a_pref.x;
        As[ak + 1][ar] = a_pref.y;
        As[ak + 2][ar] = a_pref.z;
        As[ak + 3][ar] = a_pref.w;
        *(float4*)&Bs[br][bc] = b_pref;
        __syncthreads();
        if (k0 + 8 < K) {
            a_pref = *(const float4*)(Aptr + k0 + 8);
            b_pref = *(const float4*)(Bptr + (size_t)(k0 + 8) * N);
        }
#pragma unroll
        for (int k = 0; k < 8; k++) {
            *(float4*)&a_frag[0] = *(const float4*)&As[k][tr * 4];
            *(float4*)&a_frag[4] = *(const float4*)&As[k][64 + tr * 4];
            *(float4*)&b_frag[0] = *(const float4*)&Bs[k][tc * 4];
            *(float4*)&b_frag[4] = *(const float4*)&Bs[k][64 + tc * 4];
#pragma unroll
            for (int i = 0; i < 8; i++)
#pragma unroll
                for (int j = 0; j < 8; j++)
                    acc[i][j] += a_frag[i] * b_frag[j];
        }
        __syncthreads();
    }
#pragma unroll
    for (int i = 0; i < 8; i++) {
        int row = m0 + ((i < 4) ? (tr * 4 + i) : (64 + tr * 4 + i - 4));
        float mask = 1.0f;
        if (rowcnt) {
            int bb = row / rpb, nn = row % rpb;
            if (nn >= rowcnt[bb]) mask = 0.0f;
        }
        float* crow = C + (size_t)row * ldc;
#pragma unroll
        for (int jh = 0; jh < 2; jh++) {
            int col = n0 + jh * 64 + tc * 4;
            float4 v;
            v.x = acc[i][jh * 4 + 0]; v.y = acc[i][jh * 4 + 1];
            v.z = acc[i][jh * 4 + 2]; v.w = acc[i][jh * 4 + 3];
            if (bias) {
                v.x += bias[col + 0]; v.y += bias[col + 1];
                v.z += bias[col + 2]; v.w += bias[col + 3];
            }
            if (relu) {
                v.x = fmaxf(v.x, 0.f); v.y = fmaxf(v.y, 0.f);
                v.z = fmaxf(v.z, 0.f); v.w = fmaxf(v.w, 0.f);
            }
            v.x *= mask; v.y *= mask; v.z *= mask; v.w *= mask;
            *(float4*)(crow + col) = v;
        }
    }
}

// ========== 64x64 tile GEMM, dual weight via blockIdx.z (XW / XW2) ==========
__global__ void sgemm64_dual(const float* __restrict__ A,
                             const float* __restrict__ B0, const float* __restrict__ B1,
                             float* __restrict__ C0, float* __restrict__ C1,
                             int M, int N, int K,
                             const int* __restrict__ rowcnt, int rpb)
{
    const float* Bw = blockIdx.z ? B1 : B0;
    float* C = blockIdx.z ? C1 : C0;
    __shared__ float As[16][64];
    __shared__ float Bs[16][64];
    const int tid = threadIdx.x;             // 256 threads
    const int bx = blockIdx.x, by = blockIdx.y;
    const int tx = tid & 15, ty = tid >> 4;
    const int a_row = tid >> 2, a_col = (tid & 3) << 2;
    const int b_row = tid >> 4, b_col = (tid & 15) << 2;

    const float* Ab = A + (size_t)(by * 64) * K;
    const float* Bb = Bw + (size_t)(bx * 64);

    float acc[4][4] = {};
    for (int k0 = 0; k0 < K; k0 += 16) {
        float4 av = *(const float4*)(Ab + (size_t)a_row * K + k0 + a_col);
        As[a_col + 0][a_row] = av.x;
        As[a_col + 1][a_row] = av.y;
        As[a_col + 2][a_row] = av.z;
        As[a_col + 3][a_row] = av.w;
        *(float4*)&Bs[b_row][b_col] =
            *(const float4*)(Bb + (size_t)(k0 + b_row) * N + b_col);
        __syncthreads();
#pragma unroll
        for (int k = 0; k < 16; k++) {
            float a0 = As[k][ty * 4 + 0], a1 = As[k][ty * 4 + 1];
            float a2 = As[k][ty * 4 + 2], a3 = As[k][ty * 4 + 3];
            float b0 = Bs[k][tx * 4 + 0], b1 = Bs[k][tx * 4 + 1];
            float b2 = Bs[k][tx * 4 + 2], b3 = Bs[k][tx * 4 + 3];
            acc[0][0] += a0 * b0; acc[0][1] += a0 * b1; acc[0][2] += a0 * b2; acc[0][3] += a0 * b3;
            acc[1][0] += a1 * b0; acc[1][1] += a1 * b1; acc[1][2] += a1 * b2; acc[1][3] += a1 * b3;
            acc[2][0] += a2 * b0; acc[2][1] += a2 * b1; acc[2][2] += a2 * b2; acc[2][3] += a2 * b3;
            acc[3][0] += a3 * b0; acc[3][1] += a3 * b1; acc[3][2] += a3 * b2; acc[3][3] += a3 * b3;
        }
        __syncthreads();
    }
#pragma unroll
    for (int i = 0; i < 4; i++) {
        int row = by * 64 + ty * 4 + i;
        float mask = 1.0f;
        if (rowcnt) {
            int bb = row / rpb, nn = row % rpb;
            if (nn >= rowcnt[bb]) mask = 0.0f;
        }
#pragma unroll
        for (int j = 0; j < 4; j++) {
            int col = bx * 64 + tx * 4 + j;
            C[(size_t)row * N + col] = acc[i][j] * mask;
        }
    }
}

// ------------------------- Eg gather: Eg[b,m] = EF[b,src,dst]*emask ---------
__global__ void eg_gather(const float* __restrict__ EF, const int* __restrict__ eidx,
                          const int* __restrict__ nedg, float* __restrict__ Eg)
{
    int b = blockIdx.x / M_, m = blockIdx.x % M_;
    int s = eidx[(b * 2 + 0) * M_ + m];
    int d = eidx[(b * 2 + 1) * M_ + m];
    bool on = m < nedg[b];
    const float4* src = (const float4*)(EF + (((size_t)b * N_ + s) * N_ + d) * DE_);
    float4* dst = (float4*)(Eg + ((size_t)b * M_ + m) * DE_);
    float4 z = make_float4(0.f, 0.f, 0.f, 0.f);
    for (int t = threadIdx.x; t < DE_ / 4; t += blockDim.x)
        dst[t] = on ? src[t] : z;
}

// --------- h: relu(XW_i + sum_j adj_ij*XW_j)*mask -> nemb cols [0:128) ------
__global__ void h_kernel(const float* __restrict__ XW, const float* __restrict__ adj,
                         const int* __restrict__ nobj, float* __restrict__ nemb)
{
    int b = blockIdx.x / N_, i = blockIdx.x % N_;
    int w = threadIdx.x;                    // 128
    __shared__ float arow[N_];
    arow[w] = adj[((size_t)b * N_ + i) * N_ + w];
    __syncthreads();
    const float* XWb = XW + (size_t)b * N_ * WN_;
    float acc = XWb[i * WN_ + w];           // identity term (XW row-masked)
    for (int j = 0; j < N_; j++) {
        float a = arow[j];
        if (a != 0.0f) acc += a * XWb[j * WN_ + w];
    }
    nemb[((size_t)b * N_ + i) * 256 + w] = (i < nobj[b]) ? fmaxf(acc, 0.0f) : 0.0f;
}

// ----------- g = relu(EgWe_m + sum_k L_mk * EgWe_k) * emask (sparse L) ------
__global__ void g_kernel(const float* __restrict__ EgWe, const float* __restrict__ ladj,
                         const int* __restrict__ nedg, float* __restrict__ g)
{
    int b = blockIdx.x / M_, m = blockIdx.x % M_;
    int w = threadIdx.x;                    // 128
    __shared__ int   s_idx[M_];
    __shared__ float s_val[M_];
    __shared__ int   s_cnt[129];

    const float* Lrow = ladj + ((size_t)b * M_ + m) * M_;
    float v[8];
    int cnt = 0;
    int base = w * 8;
#pragma unroll
    for (int t = 0; t < 8; t++) {
        v[t] = Lrow[base + t];
        if (v[t] != 0.0f) cnt++;
    }
    s_cnt[w + 1] = cnt;
    if (w == 0) s_cnt[0] = 0;
    __syncthreads();
    if (w == 0)
        for (int t = 1; t <= 128; t++) s_cnt[t] += s_cnt[t - 1];
    __syncthreads();
    int pos = s_cnt[w];
#pragma unroll
    for (int t = 0; t < 8; t++)
        if (v[t] != 0.0f) { s_idx[pos] = base + t; s_val[pos] = v[t]; pos++; }
    __syncthreads();
    int total = s_cnt[128];
    const float* Eb = EgWe + (size_t)b * M_ * WE_;
    float acc = Eb[m * WE_ + w];            // identity term (Eg row-masked)
    for (int p = 0; p < total; p++)
        acc += s_val[p] * Eb[s_idx[p] * WE_ + w];
    g[((size_t)b * M_ + m) * WE_ + w] = (m < nedg[b]) ? fmaxf(acc, 0.0f) : 0.0f;
}

// -------- agg[b,n] = sum_{m: src==n} g[b,m] * nmask -> nemb cols [128:256) --
__global__ void agg_kernel(const float* __restrict__ g, const int* __restrict__ eidx,
                           const int* __restrict__ nobj, float* __restrict__ nemb)
{
    int b = blockIdx.x / N_, n = blockIdx.x % N_;
    int w = threadIdx.x;                    // 128
    __shared__ int ssrc[M_];
    for (int t = w; t < M_; t += 128) ssrc[t] = eidx[(b * 2 + 0) * M_ + t];
    __syncthreads();
    float acc = 0.0f;
    const float* gb = g + (size_t)b * M_ * WE_;
    for (int m = 0; m < M_; m++)
        if (ssrc[m] == n) acc += gb[m * WE_ + w];
    nemb[((size_t)b * N_ + n) * 256 + 128 + w] = (n < nobj[b]) ? acc : 0.0f;
}

// ------------------------- edge feats gathered at pairs ---------------------
__global__ void efp_gather(const float* __restrict__ EF, const int* __restrict__ pairs,
                           float* __restrict__ EFp)
{
    int b = blockIdx.x / P_, p = blockIdx.x % P_;
    int p0 = pairs[((size_t)b * P_ + p) * 2 + 0];
    int p1 = pairs[((size_t)b * P_ + p) * 2 + 1];
    const float4* src = (const float4*)(EF + (((size_t)b * N_ + p0) * N_ + p1) * DE_);
    float4* dst = (float4*)(EFp + ((size_t)b * P_ + p) * DE_);
    for (int t = threadIdx.x; t < DE_ / 4; t += blockDim.x)
        dst[t] = src[t];
}

// -------------------- Pm = relu(XW2[p0]+XW2[p1]) -> pf cols [0:128) ---------
__global__ void pm_kernel(const float* __restrict__ XW2, const int* __restrict__ pairs,
                          float* __restrict__ pf)
{
    int b = blockIdx.x / P_, p = blockIdx.x % P_;
    int w = threadIdx.x;                    // 128
    int p0 = pairs[((size_t)b * P_ + p) * 2 + 0];
    int p1 = pairs[((size_t)b * P_ + p) * 2 + 1];
    const float* xb = XW2 + (size_t)b * N_ * WN_;
    pf[((size_t)b * P_ + p) * 256 + w] = fmaxf(xb[p0 * WN_ + w] + xb[p1 * WN_ + w], 0.0f);
}

// ------------------------- concat W1 / b1 (lr | scr | mr) -------------------
__global__ void catw1(const float* __restrict__ lrW1, const float* __restrict__ scrW1,
                      const float* __restrict__ mrW1, const float* __restrict__ lrb1,
                      const float* __restrict__ scrb1, const float* __restrict__ mrb1,
                      float* __restrict__ W1c, float* __restrict__ b1c)
{
    int k = blockIdx.x, c = threadIdx.x;    // 512 blocks, 256 threads
    W1c[k * 768 + c]       = lrW1 [k * 256 + c];
    W1c[k * 768 + 256 + c] = scrW1[k * 256 + c];
    W1c[k * 768 + 512 + c] = mrW1 [k * 256 + c];
    if (k == 0) {
        b1c[c]       = lrb1[c];
        b1c[256 + c] = scrb1[c];
        b1c[512 + c] = mrb1[c];
    }
}

// ------ layer-2 heads: hid = relu(hidB + nodeY[p0] + nodeY[p1]) fused -------
__global__ void head2_kernel(const float* __restrict__ hidB,
                             const float* __restrict__ nodeY,
                             const int* __restrict__ pairs,
                             const float* __restrict__ lrW2, const float* __restrict__ lrb2,
                             const float* __restrict__ crW2, const float* __restrict__ crb2,
                             const float* __restrict__ mrW2, const float* __restrict__ mrb2,
                             float* __restrict__ out)
{
    __shared__ float sh[8 * 768];
    __shared__ int sp[16];
    int tid = threadIdx.x;                  // 256
    int blk = blockIdx.x;                   // 8 pairs per block
    if (tid < 16) sp[tid] = pairs[(size_t)blk * 16 + tid];
    __syncthreads();
    int b = (blk * 8) / P_;                 // all 8 pairs share batch (P_%8==0)
    const float* nYb = nodeY + (size_t)b * N_ * 768;
    for (int i = tid; i < 8 * 768; i += 256) {
        int lp = i / 768, col = i - lp * 768;
        int g = blk * 8 + lp;
        float v = hidB[(size_t)g * 768 + col]
                + nYb[(size_t)sp[lp * 2 + 0] * 768 + col]
                + nYb[(size_t)sp[lp * 2 + 1] * 768 + col];
        sh[i] = fmaxf(v, 0.0f);
    }
    __syncthreads();
    int lp = tid / 32, j = tid % 32;
    int pr = blk * 8 + lp;
    const float* W2; float bias; int nout, oj; const float* hr; size_t obase;
    if (j < 9)       { W2 = lrW2; oj = j;      bias = lrb2[oj]; nout = 9;  hr = sh + lp * 768;       obase = 0; }
    else if (j < 15) { W2 = crW2; oj = j - 9;  bias = crb2[oj]; nout = 6;  hr = sh + lp * 768 + 256; obase = (size_t)B_ * P_ * 9; }
    else             { W2 = mrW2; oj = j - 15; bias = mrb2[oj]; nout = 17; hr = sh + lp * 768 + 512; obase = (size_t)B_ * P_ * 15; }
    float acc = bias;
#pragma unroll 8
    for (int k = 0; k < 256; k++)
        acc += hr[k] * W2[k * nout + oj];
    out[obase + (size_t)pr * nout + oj] = acc;
}

// ============================================================================
extern "C" void kernel_launch(void* const* d_in, const int* in_sizes, int n_in,
                              void* d_out, int out_size)
{
    const float* NF    = (const float*)d_in[0];
    const float* EF    = (const float*)d_in[1];
    const float* ADJ   = (const float*)d_in[2];
    const float* LADJ  = (const float*)d_in[3];
    const int*   EIDX  = (const int*)  d_in[4];
    const int*   PAIRS = (const int*)  d_in[5];
    const int*   NOBJ  = (const int*)  d_in[6];
    const int*   NEDG  = (const int*)  d_in[7];
    const float* Wn    = (const float*)d_in[8];
    const float* We    = (const float*)d_in[9];
    const float* Wn2   = (const float*)d_in[10];
    const float* We2   = (const float*)d_in[11];
    const float* scrW1 = (const float*)d_in[12];
    const float* scrb1 = (const float*)d_in[13];
    const float* scrW2 = (const float*)d_in[14];
    const float* scrb2 = (const float*)d_in[15];
    const float* lrW1  = (const float*)d_in[16];
    const float* lrb1  = (const float*)d_in[17];
    const float* lrW2  = (const float*)d_in[18];
    const float* lrb2  = (const float*)d_in[19];
    const float* mrW1  = (const float*)d_in[20];
    const float* mrb1  = (const float*)d_in[21];
    const float* mrW2  = (const float*)d_in[22];
    const float* mrb2  = (const float*)d_in[23];
    float* out = (float*)d_out;

    float *XW, *XW2, *nemb, *nodeY, *Eg, *EgWe, *g, *EFp, *pf, *hidB, *W1c, *b1c;
    cudaGetSymbolAddress((void**)&XW,    d_XW);
    cudaGetSymbolAddress((void**)&XW2,   d_XW2);
    cudaGetSymbolAddress((void**)&nemb,  d_nemb);
    cudaGetSymbolAddress((void**)&nodeY, d_nodeY);
    cudaGetSymbolAddress((void**)&Eg,    d_Eg);
    cudaGetSymbolAddress((void**)&EgWe,  d_EgWe);
    cudaGetSymbolAddress((void**)&g,     d_g);
    cudaGetSymbolAddress((void**)&EFp,   d_EFp);
    cudaGetSymbolAddress((void**)&pf,    d_pf);
    cudaGetSymbolAddress((void**)&hidB,  d_hidB);
    cudaGetSymbolAddress((void**)&W1c,   d_W1c);
    cudaGetSymbolAddress((void**)&b1c,   d_b1c);

    // weight concat (independent of data path)
    catw1<<<512, 256>>>(lrW1, scrW1, mrW1, lrb1, scrb1, mrb1, W1c, b1c);

    // XW = mask(NF@Wn), XW2 = mask(NF@Wn2) in one batched launch
    sgemm64_dual<<<dim3(2, 32, 2), 256>>>(NF, Wn, Wn2, XW, XW2,
                                          B_ * N_, WN_, DN_, NOBJ, N_);

    // Eg gather + EgWe = Eg @ We               [16384 x 128 x 256]
    eg_gather<<<B_ * M_, 64>>>(EF, EIDX, NEDG, Eg);
    sgemm128<<<dim3(1, 128), 256>>>(Eg, We, EgWe, B_ * M_, WE_, DE_, WE_,
                                    nullptr, 0, nullptr, 0);

    // graph convs (sparse propagate) -> nemb = [h | agg]
    h_kernel<<<B_ * N_, 128>>>(XW, ADJ, NOBJ, nemb);
    g_kernel<<<B_ * M_, 128>>>(EgWe, LADJ, NEDG, g);
    agg_kernel<<<B_ * N_, 128>>>(g, EIDX, NOBJ, nemb);

    // nodeY = nemb @ W1c[0:256,:]              [2048 x 768 x 256]
    sgemm128<<<dim3(6, 16), 256>>>(nemb, W1c, nodeY, B_ * N_, 768, 256, 768,
                                   nullptr, 0, nullptr, 0);

    // pair features pf = [Pm | Q]
    efp_gather<<<B_ * P_, 64>>>(EF, PAIRS, EFp);
    pm_kernel<<<B_ * P_, 128>>>(XW2, PAIRS, pf);
    sgemm128<<<dim3(1, 64), 256>>>(EFp, We2, pf + 128, B_ * P_, WE_, DE_, 256,
                                   nullptr, 1, nullptr, 0);   // Q with relu

    // hidB = pf @ W1c[256:512,:] + b1c (no relu; relu after node add)
    sgemm128<<<dim3(6, 64), 256>>>(pf, W1c + 256 * 768, hidB, B_ * P_, 768, 256, 768,
                                   b1c, 0, nullptr, 0);

    // fused relu-sum + layer-2 heads -> out
    head2_kernel<<<B_ * P_ / 8, 256>>>(hidB, nodeY, PAIRS,
                                       lrW2, lrb2, scrW2, scrb2, mrW2, mrb2, out);
}

// round 3
// speedup vs baseline: 1.6743x; 1.3245x over previous
#include <cuda_runtime.h>
#include <cstdint>

#define B_   16
#define N_   128
#define M_   1024
#define DN_  512
#define DE_  256
#define WN_  128
#define WE_  128
#define P_   512

// ------------------------- scratch (device globals) -------------------------
__device__ float d_XW   [B_*N_*WN_];     // X@Wn  (row-masked)
__device__ float d_XW2  [B_*N_*WN_];     // X@Wn2 (row-masked)
__device__ float d_nemb [B_*N_*256];     // [h | agg] per node
__device__ float d_nodeY[B_*N_*768];     // nemb @ W1c[0:256]
__device__ float d_Eg   [B_*M_*DE_];     // gathered edge feats * emask
__device__ float d_EgWe [B_*M_*WE_];     // Eg@We
__device__ float d_g    [B_*M_*WE_];     // relu(L@EgWe)*emask
__device__ float d_EFp  [B_*P_*DE_];     // edge_features at pairs
__device__ float d_pf   [B_*P_*256];     // [Pm | Q] per pair
__device__ float d_hidB [B_*P_*768];     // pf @ W1c[256:512] + b1c (no relu)
__device__ float d_W1c  [512*768];       // concat(lr_W1, scr_W1, mr_W1) along cols
__device__ float d_b1c  [768];
__device__ int   d_ord  [B_*M_];         // CSR edge order by src
__device__ int   d_st   [B_*(N_+1)];     // CSR bucket starts

__device__ __forceinline__ uint32_t f2tf32(float x) {
    uint32_t r;
    asm("cvt.rna.tf32.f32 %0, %1;" : "=r"(r) : "f"(x));
    return r;
}

// ================= TF32 tensor-core GEMM: 128x128 tile, 8 warps =============
// C[M,N] = A[M,K] @ B[K,N] (+bias, relu, row-mask). M%128==0, N%128==0, K%32==0.
__global__ __launch_bounds__(256)
void tgemm(const float* __restrict__ A, const float* __restrict__ Bw,
           float* __restrict__ C, int M, int N, int K, int ldc,
           const float* __restrict__ bias, int relu,
           const int* __restrict__ rowcnt, int rpb)
{
    __shared__ uint32_t As[32][136];   // [k][m], pad 8 -> conflict-free frags
    __shared__ uint32_t Bs[32][136];   // [k][n]
    const int tid  = threadIdx.x;
    const int m0 = blockIdx.y * 128, n0 = blockIdx.x * 128;
    const int lane = tid & 31, warp = tid >> 5;
    const int wm = (warp & 1) * 64, wn = (warp >> 1) * 32;
    const int g  = lane >> 2, t4 = lane & 3;

    const int am = tid >> 1;          // A loader: m row 0..127
    const int ak = (tid & 1) * 4;     //           k quad within 8
    const int bk = tid >> 5;          // B loader: k row 0..7
    const int bn = (tid & 31) * 4;    //           n quad

    float acc[4][4][4];
#pragma unroll
    for (int a = 0; a < 4; a++)
#pragma unroll
        for (int b = 0; b < 4; b++)
#pragma unroll
            for (int c = 0; c < 4; c++) acc[a][b][c] = 0.0f;

    for (int k0 = 0; k0 < K; k0 += 32) {
#pragma unroll
        for (int ks = 0; ks < 32; ks += 8) {
            float4 v = *(const float4*)(A + (size_t)(m0 + am) * K + k0 + ks + ak);
            As[ks + ak + 0][am] = f2tf32(v.x);
            As[ks + ak + 1][am] = f2tf32(v.y);
            As[ks + ak + 2][am] = f2tf32(v.z);
            As[ks + ak + 3][am] = f2tf32(v.w);
        }
#pragma unroll
        for (int ks = 0; ks < 32; ks += 8) {
            float4 v = *(const float4*)(Bw + (size_t)(k0 + ks + bk) * N + n0 + bn);
            uint32_t* p = &Bs[ks + bk][bn];
            p[0] = f2tf32(v.x); p[1] = f2tf32(v.y);
            p[2] = f2tf32(v.z); p[3] = f2tf32(v.w);
        }
        __syncthreads();
#pragma unroll
        for (int kk = 0; kk < 32; kk += 8) {
            uint32_t aF[4][4], bF[4][2];
#pragma unroll
            for (int mt = 0; mt < 4; mt++) {
                int mb = wm + mt * 16 + g;
                aF[mt][0] = As[kk + t4    ][mb];
                aF[mt][1] = As[kk + t4    ][mb + 8];
                aF[mt][2] = As[kk + t4 + 4][mb];
                aF[mt][3] = As[kk + t4 + 4][mb + 8];
            }
#pragma unroll
            for (int nt = 0; nt < 4; nt++) {
                int nb = wn + nt * 8 + g;
                bF[nt][0] = Bs[kk + t4    ][nb];
                bF[nt][1] = Bs[kk + t4 + 4][nb];
            }
#pragma unroll
            for (int mt = 0; mt < 4; mt++)
#pragma unroll
                for (int nt = 0; nt < 4; nt++)
                    asm volatile(
                        "mma.sync.aligned.m16n8k8.row.col.f32.tf32.tf32.f32 "
                        "{%0,%1,%2,%3}, {%4,%5,%6,%7}, {%8,%9}, {%0,%1,%2,%3};"
                        : "+f"(acc[mt][nt][0]), "+f"(acc[mt][nt][1]),
                          "+f"(acc[mt][nt][2]), "+f"(acc[mt][nt][3])
                        : "r"(aF[mt][0]), "r"(aF[mt][1]), "r"(aF[mt][2]), "r"(aF[mt][3]),
                          "r"(bF[nt][0]), "r"(bF[nt][1]));
        }
        __syncthreads();
    }

#pragma unroll
    for (int mt = 0; mt < 4; mt++) {
        int row0 = m0 + wm + mt * 16 + g;
        int row1 = row0 + 8;
        float mask0 = 1.0f, mask1 = 1.0f;
        if (rowcnt) {
            if (row0 % rpb >= rowcnt[row0 / rpb]) mask0 = 0.0f;
            if (row1 % rpb >= rowcnt[row1 / rpb]) mask1 = 0.0f;
        }
        float* c0p = C + (size_t)row0 * ldc;
        float* c1p = C + (size_t)row1 * ldc;
#pragma unroll
        for (int nt = 0; nt < 4; nt++) {
            int col = n0 + wn + nt * 8 + 2 * t4;
            float v0 = acc[mt][nt][0], v1 = acc[mt][nt][1];
            float v2 = acc[mt][nt][2], v3 = acc[mt][nt][3];
            if (bias) {
                float b0 = bias[col], b1 = bias[col + 1];
                v0 += b0; v1 += b1; v2 += b0; v3 += b1;
            }
            if (relu) {
                v0 = fmaxf(v0, 0.f); v1 = fmaxf(v1, 0.f);
                v2 = fmaxf(v2, 0.f); v3 = fmaxf(v3, 0.f);
            }
            float2 w0 = make_float2(v0 * mask0, v1 * mask0);
            float2 w1 = make_float2(v2 * mask1, v3 * mask1);
            *(float2*)(c0p + col) = w0;
            *(float2*)(c1p + col) = w1;
        }
    }
}

// ------------------------- Eg gather: Eg[b,m] = EF[b,src,dst]*emask ---------
__global__ void eg_gather(const float* __restrict__ EF, const int* __restrict__ eidx,
                          const int* __restrict__ nedg, float* __restrict__ Eg)
{
    int b = blockIdx.x / M_, m = blockIdx.x % M_;
    int s = eidx[(b * 2 + 0) * M_ + m];
    int d = eidx[(b * 2 + 1) * M_ + m];
    bool on = m < nedg[b];
    const float4* src = (const float4*)(EF + (((size_t)b * N_ + s) * N_ + d) * DE_);
    float4* dst = (float4*)(Eg + ((size_t)b * M_ + m) * DE_);
    float4 z = make_float4(0.f, 0.f, 0.f, 0.f);
    for (int t = threadIdx.x; t < DE_ / 4; t += blockDim.x)
        dst[t] = on ? src[t] : z;
}

// --------- h: relu(XW_i + sum_j adj_ij*XW_j)*mask -> nemb cols [0:128) ------
__global__ void h_kernel(const float* __restrict__ XW, const float* __restrict__ adj,
                         const int* __restrict__ nobj, float* __restrict__ nemb)
{
    int b = blockIdx.x / N_, i = blockIdx.x % N_;
    int w = threadIdx.x;                    // 128
    __shared__ float arow[N_];
    arow[w] = adj[((size_t)b * N_ + i) * N_ + w];
    __syncthreads();
    const float* XWb = XW + (size_t)b * N_ * WN_;
    float acc = XWb[i * WN_ + w];           // identity term (XW row-masked)
    for (int j = 0; j < N_; j++) {
        float a = arow[j];
        if (a != 0.0f) acc += a * XWb[j * WN_ + w];
    }
    nemb[((size_t)b * N_ + i) * 256 + w] = (i < nobj[b]) ? fmaxf(acc, 0.0f) : 0.0f;
}

// ----------- g = relu(EgWe_m + sum_k L_mk * EgWe_k) * emask (sparse L) ------
__global__ void g_kernel(const float* __restrict__ EgWe, const float* __restrict__ ladj,
                         const int* __restrict__ nedg, float* __restrict__ g)
{
    int b = blockIdx.x / M_, m = blockIdx.x % M_;
    int w = threadIdx.x;                    // 128
    __shared__ int   s_idx[M_];
    __shared__ float s_val[M_];
    __shared__ int   s_cnt[129];

    const float* Lrow = ladj + ((size_t)b * M_ + m) * M_;
    float v[8];
    int cnt = 0;
    int base = w * 8;
#pragma unroll
    for (int t = 0; t < 8; t++) {
        v[t] = Lrow[base + t];
        if (v[t] != 0.0f) cnt++;
    }
    s_cnt[w + 1] = cnt;
    if (w == 0) s_cnt[0] = 0;
    __syncthreads();
    if (w == 0)
        for (int t = 1; t <= 128; t++) s_cnt[t] += s_cnt[t - 1];
    __syncthreads();
    int pos = s_cnt[w];
#pragma unroll
    for (int t = 0; t < 8; t++)
        if (v[t] != 0.0f) { s_idx[pos] = base + t; s_val[pos] = v[t]; pos++; }
    __syncthreads();
    int total = s_cnt[128];
    const float* Eb = EgWe + (size_t)b * M_ * WE_;
    float acc = Eb[m * WE_ + w];            // identity term (Eg row-masked)
    for (int p = 0; p < total; p++)
        acc += s_val[p] * Eb[s_idx[p] * WE_ + w];
    g[((size_t)b * M_ + m) * WE_ + w] = (m < nedg[b]) ? fmaxf(acc, 0.0f) : 0.0f;
}

// ---------------- CSR build: bucket edges by src, stable in m ---------------
__global__ void csr_kernel(const int* __restrict__ eidx,
                           int* __restrict__ order, int* __restrict__ start)
{
    int b = blockIdx.x, m = threadIdx.x;    // 1024 threads
    __shared__ int ssrc[M_];
    __shared__ int cnt[N_ + 1];
    ssrc[m] = eidx[(b * 2 + 0) * M_ + m];
    if (m < N_ + 1) cnt[m] = 0;
    __syncthreads();
    int s = ssrc[m];
    atomicAdd(&cnt[s + 1], 1);              // int atomics: deterministic
    int rank = 0;
    for (int mm = 0; mm < m; mm++) rank += (ssrc[mm] == s);
    __syncthreads();
    if (m == 0)
        for (int i = 1; i <= N_; i++) cnt[i] += cnt[i - 1];
    __syncthreads();
    order[b * M_ + cnt[s] + rank] = m;
    if (m < N_ + 1) start[b * (N_ + 1) + m] = cnt[m];
}

// -------- agg[b,n] = sum_{m in bucket n, ascending m} g[b,m] * nmask --------
__global__ void agg2_kernel(const float* __restrict__ g, const int* __restrict__ order,
                            const int* __restrict__ start, const int* __restrict__ nobj,
                            float* __restrict__ nemb)
{
    int b = blockIdx.x / N_, n = blockIdx.x % N_;
    int w = threadIdx.x;                    // 128
    int s0 = start[b * (N_ + 1) + n], s1 = start[b * (N_ + 1) + n + 1];
    const float* gb = g + (size_t)b * M_ * WE_;
    const int* ob = order + b * M_;
    float acc = 0.0f;
    for (int i = s0; i < s1; i++)
        acc += gb[(size_t)ob[i] * WE_ + w];
    nemb[((size_t)b * N_ + n) * 256 + 128 + w] = (n < nobj[b]) ? acc : 0.0f;
}

// ------------------------- edge feats gathered at pairs ---------------------
__global__ void efp_gather(const float* __restrict__ EF, const int* __restrict__ pairs,
                           float* __restrict__ EFp)
{
    int b = blockIdx.x / P_, p = blockIdx.x % P_;
    int p0 = pairs[((size_t)b * P_ + p) * 2 + 0];
    int p1 = pairs[((size_t)b * P_ + p) * 2 + 1];
    const float4* src = (const float4*)(EF + (((size_t)b * N_ + p0) * N_ + p1) * DE_);
    float4* dst = (float4*)(EFp + ((size_t)b * P_ + p) * DE_);
    for (int t = threadIdx.x; t < DE_ / 4; t += blockDim.x)
        dst[t] = src[t];
}

// -------------------- Pm = relu(XW2[p0]+XW2[p1]) -> pf cols [0:128) ---------
__global__ void pm_kernel(const float* __restrict__ XW2, const int* __restrict__ pairs,
                          float* __restrict__ pf)
{
    int b = blockIdx.x / P_, p = blockIdx.x % P_;
    int w = threadIdx.x;                    // 128
    int p0 = pairs[((size_t)b * P_ + p) * 2 + 0];
    int p1 = pairs[((size_t)b * P_ + p) * 2 + 1];
    const float* xb = XW2 + (size_t)b * N_ * WN_;
    pf[((size_t)b * P_ + p) * 256 + w] = fmaxf(xb[p0 * WN_ + w] + xb[p1 * WN_ + w], 0.0f);
}

// ------------------------- concat W1 / b1 (lr | scr | mr) -------------------
__global__ void catw1(const float* __restrict__ lrW1, const float* __restrict__ scrW1,
                      const float* __restrict__ mrW1, const float* __restrict__ lrb1,
                      const float* __restrict__ scrb1, const float* __restrict__ mrb1,
                      float* __restrict__ W1c, float* __restrict__ b1c)
{
    int k = blockIdx.x, c = threadIdx.x;    // 512 blocks, 256 threads
    W1c[k * 768 + c]       = lrW1 [k * 256 + c];
    W1c[k * 768 + 256 + c] = scrW1[k * 256 + c];
    W1c[k * 768 + 512 + c] = mrW1 [k * 256 + c];
    if (k == 0) {
        b1c[c]       = lrb1[c];
        b1c[256 + c] = scrb1[c];
        b1c[512 + c] = mrb1[c];
    }
}

// ------ layer-2 heads: hid = relu(hidB + nodeY[p0] + nodeY[p1]) fused -------
__global__ void head2_kernel(const float* __restrict__ hidB,
                             const float* __restrict__ nodeY,
                             const int* __restrict__ pairs,
                             const float* __restrict__ lrW2, const float* __restrict__ lrb2,
                             const float* __restrict__ crW2, const float* __restrict__ crb2,
                             const float* __restrict__ mrW2, const float* __restrict__ mrb2,
                             float* __restrict__ out)
{
    __shared__ float sh[8 * 768];
    __shared__ int sp[16];
    int tid = threadIdx.x;                  // 256
    int blk = blockIdx.x;                   // 8 pairs per block
    if (tid < 16) sp[tid] = pairs[(size_t)blk * 16 + tid];
    __syncthreads();
    int b = (blk * 8) / P_;                 // all 8 pairs share batch (P_%8==0)
    const float* nYb = nodeY + (size_t)b * N_ * 768;
    for (int i = tid; i < 8 * 768; i += 256) {
        int lp = i / 768, col = i - lp * 768;
        int gg = blk * 8 + lp;
        float v = hidB[(size_t)gg * 768 + col]
                + nYb[(size_t)sp[lp * 2 + 0] * 768 + col]
                + nYb[(size_t)sp[lp * 2 + 1] * 768 + col];
        sh[i] = fmaxf(v, 0.0f);
    }
    __syncthreads();
    int lp = tid / 32, j = tid % 32;
    int pr = blk * 8 + lp;
    const float* W2; float bias; int nout, oj; const float* hr; size_t obase;
    if (j < 9)       { W2 = lrW2; oj = j;      bias = lrb2[oj]; nout = 9;  hr = sh + lp * 768;       obase = 0; }
    else if (j < 15) { W2 = crW2; oj = j - 9;  bias = crb2[oj]; nout = 6;  hr = sh + lp * 768 + 256; obase = (size_t)B_ * P_ * 9; }
    else             { W2 = mrW2; oj = j - 15; bias = mrb2[oj]; nout = 17; hr = sh + lp * 768 + 512; obase = (size_t)B_ * P_ * 15; }
    float acc = bias;
#pragma unroll 8
    for (int k = 0; k < 256; k++)
        acc += hr[k] * W2[k * nout + oj];
    out[obase + (size_t)pr * nout + oj] = acc;
}

// ============================================================================
extern "C" void kernel_launch(void* const* d_in, const int* in_sizes, int n_in,
                              void* d_out, int out_size)
{
    const float* NF    = (const float*)d_in[0];
    const float* EF    = (const float*)d_in[1];
    const float* ADJ   = (const float*)d_in[2];
    const float* LADJ  = (const float*)d_in[3];
    const int*   EIDX  = (const int*)  d_in[4];
    const int*   PAIRS = (const int*)  d_in[5];
    const int*   NOBJ  = (const int*)  d_in[6];
    const int*   NEDG  = (const int*)  d_in[7];
    const float* Wn    = (const float*)d_in[8];
    const float* We    = (const float*)d_in[9];
    const float* Wn2   = (const float*)d_in[10];
    const float* We2   = (const float*)d_in[11];
    const float* scrW1 = (const float*)d_in[12];
    const float* scrb1 = (const float*)d_in[13];
    const float* scrW2 = (const float*)d_in[14];
    const float* scrb2 = (const float*)d_in[15];
    const float* lrW1  = (const float*)d_in[16];
    const float* lrb1  = (const float*)d_in[17];
    const float* lrW2  = (const float*)d_in[18];
    const float* lrb2  = (const float*)d_in[19];
    const float* mrW1  = (const float*)d_in[20];
    const float* mrb1  = (const float*)d_in[21];
    const float* mrW2  = (const float*)d_in[22];
    const float* mrb2  = (const float*)d_in[23];
    float* out = (float*)d_out;

    float *XW, *XW2, *nemb, *nodeY, *Eg, *EgWe, *g, *EFp, *pf, *hidB, *W1c, *b1c;
    int *ord, *st;
    cudaGetSymbolAddress((void**)&XW,    d_XW);
    cudaGetSymbolAddress((void**)&XW2,   d_XW2);
    cudaGetSymbolAddress((void**)&nemb,  d_nemb);
    cudaGetSymbolAddress((void**)&nodeY, d_nodeY);
    cudaGetSymbolAddress((void**)&Eg,    d_Eg);
    cudaGetSymbolAddress((void**)&EgWe,  d_EgWe);
    cudaGetSymbolAddress((void**)&g,     d_g);
    cudaGetSymbolAddress((void**)&EFp,   d_EFp);
    cudaGetSymbolAddress((void**)&pf,    d_pf);
    cudaGetSymbolAddress((void**)&hidB,  d_hidB);
    cudaGetSymbolAddress((void**)&W1c,   d_W1c);
    cudaGetSymbolAddress((void**)&b1c,   d_b1c);
    cudaGetSymbolAddress((void**)&ord,   d_ord);
    cudaGetSymbolAddress((void**)&st,    d_st);

    // weight concat + CSR build (independent of GEMM path)
    catw1<<<512, 256>>>(lrW1, scrW1, mrW1, lrb1, scrb1, mrb1, W1c, b1c);
    csr_kernel<<<B_, 1024>>>(EIDX, ord, st);

    // XW = mask(NF@Wn), XW2 = mask(NF@Wn2)     [2048 x 128 x 512]
    tgemm<<<dim3(1, 16), 256>>>(NF, Wn,  XW,  B_ * N_, WN_, DN_, WN_, nullptr, 0, NOBJ, N_);
    tgemm<<<dim3(1, 16), 256>>>(NF, Wn2, XW2, B_ * N_, WN_, DN_, WN_, nullptr, 0, NOBJ, N_);

    // Eg gather + EgWe = Eg @ We               [16384 x 128 x 256]
    eg_gather<<<B_ * M_, 64>>>(EF, EIDX, NEDG, Eg);
    tgemm<<<dim3(1, 128), 256>>>(Eg, We, EgWe, B_ * M_, WE_, DE_, WE_, nullptr, 0, nullptr, 0);

    // graph convs (sparse propagate) -> nemb = [h | agg]
    h_kernel<<<B_ * N_, 128>>>(XW, ADJ, NOBJ, nemb);
    g_kernel<<<B_ * M_, 128>>>(EgWe, LADJ, NEDG, g);
    agg2_kernel<<<B_ * N_, 128>>>(g, ord, st, NOBJ, nemb);

    // nodeY = nemb @ W1c[0:256,:]              [2048 x 768 x 256]
    tgemm<<<dim3(6, 16), 256>>>(nemb, W1c, nodeY, B_ * N_, 768, 256, 768,
                                nullptr, 0, nullptr, 0);

    // pair features pf = [Pm | Q]
    efp_gather<<<B_ * P_, 64>>>(EF, PAIRS, EFp);
    pm_kernel<<<B_ * P_, 128>>>(XW2, PAIRS, pf);
    tgemm<<<dim3(1, 64), 256>>>(EFp, We2, pf + 128, B_ * P_, WE_, DE_, 256,
                                nullptr, 1, nullptr, 0);   // Q with relu

    // hidB = pf @ W1c[256:512,:] + b1c (no relu; relu after node add)
    tgemm<<<dim3(6, 64), 256>>>(pf, W1c + 256 * 768, hidB, B_ * P_, 768, 256, 768,
                                b1c, 0, nullptr, 0);

    // fused relu-sum + layer-2 heads -> out
    head2_kernel<<<B_ * P_ / 8, 256>>>(hidB, nodeY, PAIRS,
                                       lrW2, lrb2, scrW2, scrb2, mrW2, mrb2, out);
}

// round 5
// speedup vs baseline: 2.1200x; 1.2662x over previous
#include <cuda_runtime.h>
#include <cstdint>

#define B_   16
#define N_   128
#define M_   1024
#define DN_  512
#define DE_  256
#define WN_  128
#define WE_  128
#define P_   512

// ------------------------- scratch (device globals) -------------------------
__device__ float d_XWc  [B_*N_*256];     // [X@Wn | X@Wn2] (row-masked)
__device__ float d_nemb [B_*N_*256];     // [h | agg] per node
__device__ float d_nodeY[B_*N_*768];     // nemb @ W1c[0:256]
__device__ float d_Eg   [B_*M_*DE_];     // gathered edge feats * emask
__device__ float d_EgWe [B_*M_*WE_];     // Eg@We
__device__ float d_g    [B_*M_*WE_];     // relu(L@EgWe)*emask
__device__ float d_EFp  [B_*P_*DE_];     // edge_features at pairs
__device__ float d_pf   [B_*P_*256];     // [Pm | Q] per pair
__device__ float d_hidB [B_*P_*768];     // pf @ W1c[256:512] + b1c (no relu)
__device__ float d_Wc   [DN_*256];       // [Wn | Wn2]
__device__ float d_W1c  [512*768];       // concat(lr_W1, scr_W1, mr_W1) along cols
__device__ float d_b1c  [768];
__device__ int   d_ord  [B_*M_];         // CSR edge order by src
__device__ int   d_st   [B_*(N_+1)];     // CSR bucket starts

__device__ __forceinline__ uint32_t f2tf32(float x) {
    uint32_t r;
    asm("cvt.rna.tf32.f32 %0, %1;" : "=r"(r) : "f"(x));
    return r;
}

// ============ TF32 tensor-core GEMM tile (128x128, 8 warps), device fn ======
// Computes C tile (bx,by) of C[M,N] = A[M,K] @ B[K,N] (+bias, relu, row-mask).
// M%128==0, N%128==0, K%32==0. C may be pre-offset by caller (ldc covers it).
__device__ __forceinline__
void gemm_tile(const float* __restrict__ A, const float* __restrict__ Bw,
               float* __restrict__ C, int K, int N, int ldc,
               const float* __restrict__ bias, int relu,
               const int* __restrict__ rowcnt, int rpb,
               int bx, int by)
{
    __shared__ uint32_t As[32][136];   // [k][m], pad 8 -> conflict-free frags
    __shared__ uint32_t Bs[32][136];   // [k][n]
    const int tid  = threadIdx.x;
    const int m0 = by * 128, n0 = bx * 128;
    const int lane = tid & 31, warp = tid >> 5;
    const int wm = (warp & 1) * 64, wn = (warp >> 1) * 32;
    const int g  = lane >> 2, t4 = lane & 3;

    const int am = tid >> 1;          // A loader: m row 0..127
    const int ak = (tid & 1) * 4;     //           k quad within 8
    const int bk = tid >> 5;          // B loader: k row 0..7
    const int bn = (tid & 31) * 4;    //           n quad

    float acc[4][4][4];
#pragma unroll
    for (int a = 0; a < 4; a++)
#pragma unroll
        for (int b = 0; b < 4; b++)
#pragma unroll
            for (int c = 0; c < 4; c++) acc[a][b][c] = 0.0f;

    for (int k0 = 0; k0 < K; k0 += 32) {
#pragma unroll
        for (int ks = 0; ks < 32; ks += 8) {
            float4 v = *(const float4*)(A + (size_t)(m0 + am) * K + k0 + ks + ak);
            As[ks + ak + 0][am] = f2tf32(v.x);
            As[ks + ak + 1][am] = f2tf32(v.y);
            As[ks + ak + 2][am] = f2tf32(v.z);
            As[ks + ak + 3][am] = f2tf32(v.w);
        }
#pragma unroll
        for (int ks = 0; ks < 32; ks += 8) {
            float4 v = *(const float4*)(Bw + (size_t)(k0 + ks + bk) * N + n0 + bn);
            uint32_t* p = &Bs[ks + bk][bn];
            p[0] = f2tf32(v.x); p[1] = f2tf32(v.y);
            p[2] = f2tf32(v.z); p[3] = f2tf32(v.w);
        }
        __syncthreads();
#pragma unroll
        for (int kk = 0; kk < 32; kk += 8) {
            uint32_t aF[4][4], bF[4][2];
#pragma unroll
            for (int mt = 0; mt < 4; mt++) {
                int mb = wm + mt * 16 + g;
                aF[mt][0] = As[kk + t4    ][mb];
                aF[mt][1] = As[kk + t4    ][mb + 8];
                aF[mt][2] = As[kk + t4 + 4][mb];
                aF[mt][3] = As[kk + t4 + 4][mb + 8];
            }
#pragma unroll
            for (int nt = 0; nt < 4; nt++) {
                int nb = wn + nt * 8 + g;
                bF[nt][0] = Bs[kk + t4    ][nb];
                bF[nt][1] = Bs[kk + t4 + 4][nb];
            }
#pragma unroll
            for (int mt = 0; mt < 4; mt++)
#pragma unroll
                for (int nt = 0; nt < 4; nt++)
                    asm volatile(
                        "mma.sync.aligned.m16n8k8.row.col.f32.tf32.tf32.f32 "
                        "{%0,%1,%2,%3}, {%4,%5,%6,%7}, {%8,%9}, {%0,%1,%2,%3};"
                        : "+f"(acc[mt][nt][0]), "+f"(acc[mt][nt][1]),
                          "+f"(acc[mt][nt][2]), "+f"(acc[mt][nt][3])
                        : "r"(aF[mt][0]), "r"(aF[mt][1]), "r"(aF[mt][2]), "r"(aF[mt][3]),
                          "r"(bF[nt][0]), "r"(bF[nt][1]));
        }
        __syncthreads();
    }

#pragma unroll
    for (int mt = 0; mt < 4; mt++) {
        int row0 = m0 + wm + mt * 16 + g;
        int row1 = row0 + 8;
        float mask0 = 1.0f, mask1 = 1.0f;
        if (rowcnt) {
            if (row0 % rpb >= rowcnt[row0 / rpb]) mask0 = 0.0f;
            if (row1 % rpb >= rowcnt[row1 / rpb]) mask1 = 0.0f;
        }
        float* c0p = C + (size_t)row0 * ldc;
        float* c1p = C + (size_t)row1 * ldc;
#pragma unroll
        for (int nt = 0; nt < 4; nt++) {
            int col = n0 + wn + nt * 8 + 2 * t4;
            float v0 = acc[mt][nt][0], v1 = acc[mt][nt][1];
            float v2 = acc[mt][nt][2], v3 = acc[mt][nt][3];
            if (bias) {
                float b0 = bias[col], b1 = bias[col + 1];
                v0 += b0; v1 += b1; v2 += b0; v3 += b1;
            }
            if (relu) {
                v0 = fmaxf(v0, 0.f); v1 = fmaxf(v1, 0.f);
                v2 = fmaxf(v2, 0.f); v3 = fmaxf(v3, 0.f);
            }
            float2 w0 = make_float2(v0 * mask0, v1 * mask0);
            float2 w1 = make_float2(v2 * mask1, v3 * mask1);
            *(float2*)(c0p + col) = w0;
            *(float2*)(c1p + col) = w1;
        }
    }
}

// ---- batch A: XWc (32 tiles, K=512) | EgWe (128 tiles) | Q (64 tiles) ------
__global__ __launch_bounds__(256)
void gemm_batchA(const float* __restrict__ NF, const float* __restrict__ We,
                 const float* __restrict__ We2, const int* __restrict__ NOBJ)
{
    int bid = blockIdx.x;
    if (bid < 32) {
        // XWc = mask(NF @ [Wn|Wn2])          [2048 x 256 x 512]
        gemm_tile(NF, d_Wc, d_XWc, DN_, 256, 256, nullptr, 0, NOBJ, N_,
                  bid & 1, bid >> 1);
    } else if (bid < 160) {
        // EgWe = Eg @ We                     [16384 x 128 x 256]
        int t = bid - 32;
        gemm_tile(d_Eg, We, d_EgWe, DE_, WE_, WE_, nullptr, 0, nullptr, 0, 0, t);
    } else {
        // Q = relu(EFp @ We2) -> pf cols [128:256), ldc=256
        int t = bid - 160;
        gemm_tile(d_EFp, We2, d_pf + 128, DE_, WE_, 256,
                  nullptr, 1, nullptr, 0, 0, t);
    }
}

// ---- batch B: hidB (384 tiles) | nodeY (96 tiles) --------------------------
__global__ __launch_bounds__(256)
void gemm_batchB()
{
    int bid = blockIdx.x;
    if (bid < 384) {
        // hidB = pf @ W1c[256:512,:] + b1c   [8192 x 768 x 256]
        gemm_tile(d_pf, d_W1c + 256 * 768, d_hidB, 256, 768, 768,
                  d_b1c, 0, nullptr, 0, bid % 6, bid / 6);
    } else {
        // nodeY = nemb @ W1c[0:256,:]        [2048 x 768 x 256]
        int t = bid - 384;
        gemm_tile(d_nemb, d_W1c, d_nodeY, 256, 768, 768,
                  nullptr, 0, nullptr, 0, t % 6, t / 6);
    }
}

// ------------------------- Eg gather: Eg[b,m] = EF[b,src,dst]*emask ---------
__global__ void eg_gather(const float* __restrict__ EF, const int* __restrict__ eidx,
                          const int* __restrict__ nedg, float* __restrict__ Eg)
{
    int b = blockIdx.x / M_, m = blockIdx.x % M_;
    int s = eidx[(b * 2 + 0) * M_ + m];
    int d = eidx[(b * 2 + 1) * M_ + m];
    bool on = m < nedg[b];
    const float4* src = (const float4*)(EF + (((size_t)b * N_ + s) * N_ + d) * DE_);
    float4* dst = (float4*)(Eg + ((size_t)b * M_ + m) * DE_);
    float4 z = make_float4(0.f, 0.f, 0.f, 0.f);
    for (int t = threadIdx.x; t < DE_ / 4; t += blockDim.x)
        dst[t] = on ? src[t] : z;
}

// --------- h: relu(XW_i + sum_j adj_ij*XW_j)*mask -> nemb cols [0:128) ------
__global__ void h_kernel(const float* __restrict__ XWc, const float* __restrict__ adj,
                         const int* __restrict__ nobj, float* __restrict__ nemb)
{
    int b = blockIdx.x / N_, i = blockIdx.x % N_;
    int w = threadIdx.x;                    // 128
    __shared__ float arow[N_];
    arow[w] = adj[((size_t)b * N_ + i) * N_ + w];
    __syncthreads();
    const float* XWb = XWc + (size_t)b * N_ * 256;   // cols [0:128) of XWc
    float acc = XWb[i * 256 + w];           // identity term (row-masked)
    for (int j = 0; j < N_; j++) {
        float a = arow[j];
        if (a != 0.0f) acc += a * XWb[j * 256 + w];
    }
    nemb[((size_t)b * N_ + i) * 256 + w] = (i < nobj[b]) ? fmaxf(acc, 0.0f) : 0.0f;
}

// ----------- g = relu(EgWe_m + sum_k L_mk * EgWe_k) * emask (sparse L) ------
__global__ void g_kernel(const float* __restrict__ EgWe, const float* __restrict__ ladj,
                         const int* __restrict__ nedg, float* __restrict__ g)
{
    int b = blockIdx.x / M_, m = blockIdx.x % M_;
    int w = threadIdx.x;                    // 128
    __shared__ int   s_idx[M_];
    __shared__ float s_val[M_];
    __shared__ int   s_cnt[129];

    const float* Lrow = ladj + ((size_t)b * M_ + m) * M_;
    float v[8];
    int cnt = 0;
    int base = w * 8;
#pragma unroll
    for (int t = 0; t < 8; t++) {
        v[t] = Lrow[base + t];
        if (v[t] != 0.0f) cnt++;
    }
    s_cnt[w + 1] = cnt;
    if (w == 0) s_cnt[0] = 0;
    __syncthreads();
    if (w == 0)
        for (int t = 1; t <= 128; t++) s_cnt[t] += s_cnt[t - 1];
    __syncthreads();
    int pos = s_cnt[w];
#pragma unroll
    for (int t = 0; t < 8; t++)
        if (v[t] != 0.0f) { s_idx[pos] = base + t; s_val[pos] = v[t]; pos++; }
    __syncthreads();
    int total = s_cnt[128];
    const float* Eb = EgWe + (size_t)b * M_ * WE_;
    float acc = Eb[m * WE_ + w];            // identity term (Eg row-masked)
    for (int p = 0; p < total; p++)
        acc += s_val[p] * Eb[s_idx[p] * WE_ + w];
    g[((size_t)b * M_ + m) * WE_ + w] = (m < nedg[b]) ? fmaxf(acc, 0.0f) : 0.0f;
}

// ---------------- CSR build: bucket edges by src, stable in m ---------------
__global__ void csr_kernel(const int* __restrict__ eidx,
                           int* __restrict__ order, int* __restrict__ start)
{
    int b = blockIdx.x, m = threadIdx.x;    // 1024 threads
    __shared__ int ssrc[M_];
    __shared__ int cnt[N_ + 1];
    ssrc[m] = eidx[(b * 2 + 0) * M_ + m];
    if (m < N_ + 1) cnt[m] = 0;
    __syncthreads();
    int s = ssrc[m];
    atomicAdd(&cnt[s + 1], 1);              // int atomics: deterministic
    int rank = 0;
    for (int mm = 0; mm < m; mm++) rank += (ssrc[mm] == s);
    __syncthreads();
    if (m == 0)
        for (int i = 1; i <= N_; i++) cnt[i] += cnt[i - 1];
    __syncthreads();
    order[b * M_ + cnt[s] + rank] = m;
    if (m < N_ + 1) start[b * (N_ + 1) + m] = cnt[m];
}

// -------- agg[b,n] = sum_{m in bucket n, ascending m} g[b,m] * nmask --------
__global__ void agg2_kernel(const float* __restrict__ g, const int* __restrict__ order,
                            const int* __restrict__ start, const int* __restrict__ nobj,
                            float* __restrict__ nemb)
{
    int b = blockIdx.x / N_, n = blockIdx.x % N_;
    int w = threadIdx.x;                    // 128
    int s0 = start[b * (N_ + 1) + n], s1 = start[b * (N_ + 1) + n + 1];
    const float* gb = g + (size_t)b * M_ * WE_;
    const int* ob = order + b * M_;
    float acc = 0.0f;
    for (int i = s0; i < s1; i++)
        acc += gb[(size_t)ob[i] * WE_ + w];
    nemb[((size_t)b * N_ + n) * 256 + 128 + w] = (n < nobj[b]) ? acc : 0.0f;
}

// ------------------------- edge feats gathered at pairs ---------------------
__global__ void efp_gather(const float* __restrict__ EF, const int* __restrict__ pairs,
                           float* __restrict__ EFp)
{
    int b = blockIdx.x / P_, p = blockIdx.x % P_;
    int p0 = pairs[((size_t)b * P_ + p) * 2 + 0];
    int p1 = pairs[((size_t)b * P_ + p) * 2 + 1];
    const float4* src = (const float4*)(EF + (((size_t)b * N_ + p0) * N_ + p1) * DE_);
    float4* dst = (float4*)(EFp + ((size_t)b * P_ + p) * DE_);
    for (int t = threadIdx.x; t < DE_ / 4; t += blockDim.x)
        dst[t] = src[t];
}

// -------------------- Pm = relu(XW2[p0]+XW2[p1]) -> pf cols [0:128) ---------
__global__ void pm_kernel(const float* __restrict__ XWc, const int* __restrict__ pairs,
                          float* __restrict__ pf)
{
    int b = blockIdx.x / P_, p = blockIdx.x % P_;
    int w = threadIdx.x;                    // 128
    int p0 = pairs[((size_t)b * P_ + p) * 2 + 0];
    int p1 = pairs[((size_t)b * P_ + p) * 2 + 1];
    const float* xb = XWc + (size_t)b * N_ * 256 + 128;   // cols [128:256)
    pf[((size_t)b * P_ + p) * 256 + w] =
        fmaxf(xb[(size_t)p0 * 256 + w] + xb[(size_t)p1 * 256 + w], 0.0f);
}

// --------------- concat weights: Wc=[Wn|Wn2], W1c, b1c ----------------------
__global__ void catw1(const float* __restrict__ Wn, const float* __restrict__ Wn2,
                      const float* __restrict__ lrW1, const float* __restrict__ scrW1,
                      const float* __restrict__ mrW1, const float* __restrict__ lrb1,
                      const float* __restrict__ scrb1, const float* __restrict__ mrb1)
{
    int k = blockIdx.x, c = threadIdx.x;    // 512 blocks, 256 threads
    d_W1c[k * 768 + c]       = lrW1 [k * 256 + c];
    d_W1c[k * 768 + 256 + c] = scrW1[k * 256 + c];
    d_W1c[k * 768 + 512 + c] = mrW1 [k * 256 + c];
    d_Wc[k * 256 + c] = (c < 128) ? Wn[k * 128 + c] : Wn2[k * 128 + (c - 128)];
    if (k == 0) {
        d_b1c[c]       = lrb1[c];
        d_b1c[256 + c] = scrb1[c];
        d_b1c[512 + c] = mrb1[c];
    }
}

// ------ layer-2 heads: hid = relu(hidB + nodeY[p0] + nodeY[p1]) fused -------
__global__ void head2_kernel(const float* __restrict__ hidB,
                             const float* __restrict__ nodeY,
                             const int* __restrict__ pairs,
                             const float* __restrict__ lrW2, const float* __restrict__ lrb2,
                             const float* __restrict__ crW2, const float* __restrict__ crb2,
                             const float* __restrict__ mrW2, const float* __restrict__ mrb2,
                             float* __restrict__ out)
{
    __shared__ float sh[8 * 768];
    __shared__ int sp[16];
    int tid = threadIdx.x;                  // 256
    int blk = blockIdx.x;                   // 8 pairs per block
    if (tid < 16) sp[tid] = pairs[(size_t)blk * 16 + tid];
    __syncthreads();
    int b = (blk * 8) / P_;                 // all 8 pairs share batch (P_%8==0)
    const float* nYb = nodeY + (size_t)b * N_ * 768;
    for (int i = tid; i < 8 * 768; i += 256) {
        int lp = i / 768, col = i - lp * 768;
        int gg = blk * 8 + lp;
        float v = hidB[(size_t)gg * 768 + col]
                + nYb[(size_t)sp[lp * 2 + 0] * 768 + col]
                + nYb[(size_t)sp[lp * 2 + 1] * 768 + col];
        sh[i] = fmaxf(v, 0.0f);
    }
    __syncthreads();
    int lp = tid / 32, j = tid % 32;
    int pr = blk * 8 + lp;
    const float* W2; float bias; int nout, oj; const float* hr; size_t obase;
    if (j < 9)       { W2 = lrW2; oj = j;      bias = lrb2[oj]; nout = 9;  hr = sh + lp * 768;       obase = 0; }
    else if (j < 15) { W2 = crW2; oj = j - 9;  bias = crb2[oj]; nout = 6;  hr = sh + lp * 768 + 256; obase = (size_t)B_ * P_ * 9; }
    else             { W2 = mrW2; oj = j - 15; bias = mrb2[oj]; nout = 17; hr = sh + lp * 768 + 512; obase = (size_t)B_ * P_ * 15; }
    float acc = bias;
#pragma unroll 8
    for (int k = 0; k < 256; k++)
        acc += hr[k] * W2[k * nout + oj];
    out[obase + (size_t)pr * nout + oj] = acc;
}

// ============================================================================
extern "C" void kernel_launch(void* const* d_in, const int* in_sizes, int n_in,
                              void* d_out, int out_size)
{
    const float* NF    = (const float*)d_in[0];
    const float* EF    = (const float*)d_in[1];
    const float* ADJ   = (const float*)d_in[2];
    const float* LADJ  = (const float*)d_in[3];
    const int*   EIDX  = (const int*)  d_in[4];
    const int*   PAIRS = (const int*)  d_in[5];
    const int*   NOBJ  = (const int*)  d_in[6];
    const int*   NEDG  = (const int*)  d_in[7];
    const float* Wn    = (const float*)d_in[8];
    const float* We    = (const float*)d_in[9];
    const float* Wn2   = (const float*)d_in[10];
    const float* We2   = (const float*)d_in[11];
    const float* scrW1 = (const float*)d_in[12];
    const float* scrb1 = (const float*)d_in[13];
    const float* scrW2 = (const float*)d_in[14];
    const float* scrb2 = (const float*)d_in[15];
    const float* lrW1  = (const float*)d_in[16];
    const float* lrb1  = (const float*)d_in[17];
    const float* lrW2  = (const float*)d_in[18];
    const float* lrb2  = (const float*)d_in[19];
    const float* mrW1  = (const float*)d_in[20];
    const float* mrb1  = (const float*)d_in[21];
    const float* mrW2  = (const float*)d_in[22];
    const float* mrb2  = (const float*)d_in[23];
    float* out = (float*)d_out;

    float *XWc, *nemb, *nodeY, *Eg, *EgWe, *g, *EFp, *pf, *hidB;
    int *ord, *st;
    cudaGetSymbolAddress((void**)&XWc,   d_XWc);
    cudaGetSymbolAddress((void**)&nemb,  d_nemb);
    cudaGetSymbolAddress((void**)&nodeY, d_nodeY);
    cudaGetSymbolAddress((void**)&Eg,    d_Eg);
    cudaGetSymbolAddress((void**)&EgWe,  d_EgWe);
    cudaGetSymbolAddress((void**)&g,     d_g);
    cudaGetSymbolAddress((void**)&EFp,   d_EFp);
    cudaGetSymbolAddress((void**)&pf,    d_pf);
    cudaGetSymbolAddress((void**)&hidB,  d_hidB);
    cudaGetSymbolAddress((void**)&ord,   d_ord);
    cudaGetSymbolAddress((void**)&st,    d_st);

    // stage 1: gathers + weight concat + CSR (all independent)
    catw1<<<512, 256>>>(Wn, Wn2, lrW1, scrW1, mrW1, lrb1, scrb1, mrb1);
    csr_kernel<<<B_, 1024>>>(EIDX, ord, st);
    eg_gather<<<B_ * M_, 64>>>(EF, EIDX, NEDG, Eg);
    efp_gather<<<B_ * P_, 64>>>(EF, PAIRS, EFp);

    // stage 2: batched GEMM A — XWc(32,K=512) | EgWe(128) | Q->pf[:,128:](64)
    gemm_batchA<<<224, 256>>>(NF, We, We2, NOBJ);

    // stage 3: graph convs + pair Pm
    h_kernel<<<B_ * N_, 128>>>(XWc, ADJ, NOBJ, nemb);
    g_kernel<<<B_ * M_, 128>>>(EgWe, LADJ, NEDG, g);
    pm_kernel<<<B_ * P_, 128>>>(XWc, PAIRS, pf);
    agg2_kernel<<<B_ * N_, 128>>>(g, ord, st, NOBJ, nemb);

    // stage 4: batched GEMM B — hidB(384) | nodeY(96)
    gemm_batchB<<<480, 256>>>();

    // stage 5: fused relu-sum + layer-2 heads -> out
    head2_kernel<<<B_ * P_ / 8, 256>>>(hidB, nodeY, PAIRS,
                                       lrW2, lrb2, scrW2, scrb2, mrW2, mrb2, out);
}